// round 10
// baseline (speedup 1.0000x reference)
#include <cuda_runtime.h>
#include <stdint.h>

#define N_BCH 8
#define N_ATM 10000
#define N_ELM 100
#define THREADS 1024
#define NWARP  32
#define GRID_MAIN 148            // 1 CTA per SM
#define STAGES 3

#define ELM_BYTES (N_BCH * N_ATM)               // 80000
// smem layout (bytes)
#define SMEM_ACC   0                            // 32 warps * 256 floats = 32768
#define SMEM_LUT   (NWARP * 256 * 4)            // 1024
#define SMEM_ELM   (SMEM_LUT + 1024)            // 80000 -> ends 113792
#define SMEM_BUF   (SMEM_ELM + ELM_BYTES)
#define ARR_B      (THREADS * 8)                // 8192 per array per stage
#define STG_B      (4 * ARR_B)                  // 32768 per stage
#define SMEM_TOTAL (SMEM_BUF + STAGES * STG_B)  // 212096 B

__device__ uint8_t g_elm8[ELM_BYTES];

__device__ __forceinline__ float fsqrt_approx(float x)
{
    float y;
    asm("sqrt.approx.f32 %0, %1;" : "=f"(y) : "f"(x));
    return y;
}

__device__ __forceinline__ void cp8(uint32_t saddr, const void* gptr)
{
    asm volatile("cp.async.ca.shared.global [%0], [%1], 8;\n"
                 :: "r"(saddr), "l"(gptr));
}
__device__ __forceinline__ void cp_commit()
{
    asm volatile("cp.async.commit_group;\n");
}
template <int N>
__device__ __forceinline__ void cp_wait()
{
    asm volatile("cp.async.wait_group %0;\n" :: "n"(N));
}

__device__ __forceinline__ uint32_t smem_u32(const void* p)
{
    uint32_t a;
    asm("{ .reg .u64 t; cvta.to.shared.u64 t, %1; cvt.u32.u64 %0, t; }"
        : "=r"(a) : "l"(p));
    return a;
}

// ---------------------------------------------------------------------------
// Prepass: zero outputs, convert elm int32 -> uint8 (values < 100).
// ---------------------------------------------------------------------------
__global__ void prep_kernel(const int* __restrict__ elm, float* __restrict__ out)
{
    int tid = blockIdx.x * blockDim.x + threadIdx.x;
    if (tid < N_BCH) out[tid] = 0.0f;
    for (int i = tid; i < ELM_BYTES; i += gridDim.x * blockDim.x)
        g_elm8[i] = (uint8_t)elm[i];
}

// ---------------------------------------------------------------------------
// Per-edge work: smem gathers + smem RMW accumulate.
// ---------------------------------------------------------------------------
__device__ __forceinline__ void edge_op(int n, int i, int j, float s,
                                        const uint8_t* __restrict__ elm_s,
                                        const float2* __restrict__ lut,
                                        float* __restrict__ acc_base)
{
    int ea = elm_s[n * N_ATM + i];
    int eb = elm_s[n * N_ATM + j];
    float2 pa = lut[ea];
    float2 pb = lut[eb];
    float R   = pa.y + pb.y;
    float dis = fsqrt_approx(s);
    if (dis < R) {
        float d = dis - R;
        acc_base[n << 5] += (pa.x + pb.x) * d * d;
    }
}

__global__ void __launch_bounds__(THREADS, 1)
close_penalty_kernel(const int2*  __restrict__ edge_n2,
                     const int2*  __restrict__ edge_i2,
                     const int2*  __restrict__ edge_j2,
                     const float2* __restrict__ sod2,
                     const int*   __restrict__ edge_n,
                     const int*   __restrict__ edge_i,
                     const int*   __restrict__ edge_j,
                     const float* __restrict__ sod,
                     const float* __restrict__ k,
                     const float* __restrict__ radius,
                     float* __restrict__ out,
                     int nvec2, int E)
{
    extern __shared__ char smem[];
    float*   acc   = (float*)  (smem + SMEM_ACC);
    float2*  lut   = (float2*) (smem + SMEM_LUT);
    uint8_t* elm_s = (uint8_t*)(smem + SMEM_ELM);
    char*    buf   = smem + SMEM_BUF;           // [stage][array][tid] 8B slots

    int tid  = threadIdx.x;
    int lane = tid & 31;
    int wid  = tid >> 5;

    if (tid < N_ELM) lut[tid] = make_float2(__ldg(&k[tid]), __ldg(&radius[tid]));
    #pragma unroll
    for (int b = 0; b < 8; b++) acc[b * THREADS + tid] = 0.0f;

    // Copy 80 KB u8 element table into shared memory (16B chunks).
    {
        const int4* src = (const int4*)g_elm8;
        int4*       dst = (int4*)elm_s;
        for (int i = tid; i < ELM_BYTES / 16; i += THREADS)
            dst[i] = __ldg(&src[i]);
    }
    __syncthreads();

    float* acc_base = &acc[(wid << 8) | lane];   // + (n<<5) per edge

    uint32_t my_slot = smem_u32(buf) + (uint32_t)tid * 8;

    int nblk = (nvec2 + THREADS - 1) / THREADS;  // blocks of 1024 pairs

    auto stage = [&](int blk, int s) {
        long base = (long)blk * THREADS + tid;
        if (blk < nblk && base < nvec2) {
            uint32_t so = my_slot + (uint32_t)s * STG_B;
            cp8(so + 0 * ARR_B, &edge_n2[base]);
            cp8(so + 1 * ARR_B, &edge_i2[base]);
            cp8(so + 2 * ARR_B, &edge_j2[base]);
            cp8(so + 3 * ARR_B, &sod2[base]);
        }
    };

    // Prologue: fill STAGES-1 stages.
    #pragma unroll
    for (int p = 0; p < STAGES - 1; p++) {
        stage(blockIdx.x + p * gridDim.x, p);
        cp_commit();
    }

    // Main pipelined loop.
    for (int it = 0; ; it++) {
        int blk_cons = blockIdx.x + it * gridDim.x;
        if (blk_cons >= nblk) break;

        stage(blockIdx.x + (it + STAGES - 1) * gridDim.x,
              (it + STAGES - 1) % STAGES);
        cp_commit();
        cp_wait<STAGES - 1>();

        long base = (long)blk_cons * THREADS + tid;
        if (base < nvec2) {
            int s = it % STAGES;
            const char* sp = buf + (size_t)s * STG_B + (size_t)tid * 8;
            int2   en = *(const int2*)  (sp + 0 * ARR_B);
            int2   ei = *(const int2*)  (sp + 1 * ARR_B);
            int2   ej = *(const int2*)  (sp + 2 * ARR_B);
            float2 sd = *(const float2*)(sp + 3 * ARR_B);

            edge_op(en.x, ei.x, ej.x, sd.x, elm_s, lut, acc_base);
            edge_op(en.y, ei.y, ej.y, sd.y, elm_s, lut, acc_base);
        }
    }
    cp_wait<0>();

    // Scalar tail (E odd)
    int gtid = blockIdx.x * THREADS + tid;
    int t = nvec2 * 2 + gtid;
    if (t < E)
        edge_op(edge_n[t], edge_i[t], edge_j[t], sod[t], elm_s, lut, acc_base);

    __syncthreads();

    // Reduce: first 256 threads; thread owns (bin = tid>>5, lane).
    if (tid < 256) {
        int bin = tid >> 5;
        float sum = 0.0f;
        #pragma unroll
        for (int w = 0; w < NWARP; w++)
            sum += acc[(w << 8) + (bin << 5) + lane];
        #pragma unroll
        for (int off = 16; off > 0; off >>= 1)
            sum += __shfl_down_sync(0xFFFFFFFFu, sum, off);
        if (lane == 0)
            atomicAdd(&out[bin], sum);
    }
}

// ---------------------------------------------------------------------------
// Launch
// ---------------------------------------------------------------------------
extern "C" void kernel_launch(void* const* d_in, const int* in_sizes, int n_in,
                              void* d_out, int out_size)
{
    const int*   elm    = (const int*)  d_in[0];
    const int*   edge_n = (const int*)  d_in[1];
    const int*   edge_i = (const int*)  d_in[2];
    const int*   edge_j = (const int*)  d_in[3];
    const float* sod    = (const float*)d_in[4];
    const float* k      = (const float*)d_in[5];
    const float* radius = (const float*)d_in[6];
    float* out = (float*)d_out;

    int E     = in_sizes[1];
    int nvec2 = E >> 1;

    cudaFuncSetAttribute(close_penalty_kernel,
                         cudaFuncAttributeMaxDynamicSharedMemorySize, SMEM_TOTAL);

    prep_kernel<<<(ELM_BYTES + 255) / 256, 256>>>(elm, out);

    int grid = GRID_MAIN;
    int nblk = (nvec2 + THREADS - 1) / THREADS;
    if (nblk < grid) grid = nblk > 0 ? nblk : 1;

    close_penalty_kernel<<<grid, THREADS, SMEM_TOTAL>>>(
        (const int2*)edge_n, (const int2*)edge_i, (const int2*)edge_j,
        (const float2*)sod,
        edge_n, edge_i, edge_j, sod,
        k, radius,
        out, nvec2, E);
}

// round 11
// speedup vs baseline: 1.2031x; 1.2031x over previous
#include <cuda_runtime.h>
#include <cuda_fp16.h>
#include <stdint.h>

#define N_BCH 8
#define N_ATM 10000
#define N_ELM 100
#define THREADS 512
#define NWARP  16
#define GRID_MAIN 148            // 1 CTA per SM
#define STAGES 2

#define ELM_BYTES  (N_BCH * N_ATM)              // 80000
#define PAIR_N     (N_ELM * N_ELM)              // 10000
// smem layout (bytes)
#define SMEM_ACC   0                            // 16*256 floats = 16384
#define SMEM_PAIR  16384                        // 10000 half2 = 40000
#define SMEM_ELM   (SMEM_PAIR + PAIR_N * 4)     // 56384 (16B aligned)
#define SMEM_BUF   (SMEM_ELM + ELM_BYTES)       // 136384 (16B aligned)
#define ARR_B      (THREADS * 16)               // 8192
#define STG_B      (4 * ARR_B)                  // 32768
#define SMEM_TOTAL (SMEM_BUF + STAGES * STG_B)  // 201920

__device__ uint8_t g_elm8[ELM_BYTES];

__device__ __forceinline__ float fsqrt_approx(float x)
{
    float y;
    asm("sqrt.approx.f32 %0, %1;" : "=f"(y) : "f"(x));
    return y;
}

__device__ __forceinline__ void cp16(uint32_t saddr, const void* gptr)
{
    asm volatile("cp.async.cg.shared.global [%0], [%1], 16;\n"
                 :: "r"(saddr), "l"(gptr));
}
__device__ __forceinline__ void cp_commit()
{
    asm volatile("cp.async.commit_group;\n");
}
template <int N>
__device__ __forceinline__ void cp_wait()
{
    asm volatile("cp.async.wait_group %0;\n" :: "n"(N));
}

__device__ __forceinline__ uint32_t smem_u32(const void* p)
{
    uint32_t a;
    asm("{ .reg .u64 t; cvta.to.shared.u64 t, %1; cvt.u32.u64 %0, t; }"
        : "=r"(a) : "l"(p));
    return a;
}

// ---------------------------------------------------------------------------
// Prepass: zero outputs, convert elm int32 -> uint8 (values < 100).
// ---------------------------------------------------------------------------
__global__ void prep_kernel(const int* __restrict__ elm, float* __restrict__ out)
{
    int tid = blockIdx.x * blockDim.x + threadIdx.x;
    if (tid < N_BCH) out[tid] = 0.0f;
    for (int i = tid; i < ELM_BYTES; i += gridDim.x * blockDim.x)
        g_elm8[i] = (uint8_t)elm[i];
}

// ---------------------------------------------------------------------------
// Per-edge work: 2 u8 elm gathers + 1 half2 pair gather + smem RMW.
// ---------------------------------------------------------------------------
__device__ __forceinline__ void edge_op(int n, int i, int j, float s,
                                        const uint8_t* __restrict__ elm_s,
                                        const __half2* __restrict__ pair,
                                        float* __restrict__ acc_base)
{
    int nb = n * N_ATM;
    int ea = elm_s[nb + i];
    int eb = elm_s[nb + j];
    __half2 h = pair[ea * N_ELM + eb];
    float kk = __low2float(h);
    float R  = __high2float(h);
    float dis = fsqrt_approx(s);
    if (dis < R) {
        float d = dis - R;
        acc_base[n << 5] += kk * d * d;
    }
}

__global__ void __launch_bounds__(THREADS, 1)
close_penalty_kernel(const int4*  __restrict__ edge_n4,
                     const int4*  __restrict__ edge_i4,
                     const int4*  __restrict__ edge_j4,
                     const float4* __restrict__ sod4,
                     const int*   __restrict__ edge_n,
                     const int*   __restrict__ edge_i,
                     const int*   __restrict__ edge_j,
                     const float* __restrict__ sod,
                     const float* __restrict__ k,
                     const float* __restrict__ radius,
                     float* __restrict__ out,
                     int nvec, int E)
{
    extern __shared__ char smem[];
    float*   acc   = (float*)  (smem + SMEM_ACC);
    __half2* pair  = (__half2*)(smem + SMEM_PAIR);
    uint8_t* elm_s = (uint8_t*)(smem + SMEM_ELM);
    char*    buf   = smem + SMEM_BUF;

    int tid  = threadIdx.x;
    int lane = tid & 31;
    int wid  = tid >> 5;

    #pragma unroll
    for (int b = 0; b < 8; b++) acc[b * THREADS + tid] = 0.0f;

    // Build fused (kk, R) half2 pair table: 10000 entries.
    for (int idx = tid; idx < PAIR_N; idx += THREADS) {
        int a = idx / N_ELM;
        int b = idx - a * N_ELM;
        float kk = __ldg(&k[a]) + __ldg(&k[b]);
        float R  = __ldg(&radius[a]) + __ldg(&radius[b]);
        pair[idx] = __floats2half2_rn(kk, R);
    }

    // Copy 80 KB u8 element table into shared memory (16B chunks).
    {
        const int4* src = (const int4*)g_elm8;
        int4*       dst = (int4*)buf ? (int4*)(smem + SMEM_ELM) : nullptr;
        int4*       d2  = (int4*)(smem + SMEM_ELM);
        (void)dst;
        for (int i = tid; i < ELM_BYTES / 16; i += THREADS)
            d2[i] = __ldg(&src[i]);
    }
    __syncthreads();

    float* acc_base = &acc[(wid << 8) | lane];   // + (n<<5) per edge

    uint32_t my_slot = smem_u32(buf) + (uint32_t)tid * 16;

    int nblk = (nvec + THREADS - 1) / THREADS;   // blocks of 512 vec4 groups

    auto stage = [&](int blk, int s) {
        long base = (long)blk * THREADS + tid;
        if (blk < nblk && base < nvec) {
            uint32_t so = my_slot + (uint32_t)s * STG_B;
            cp16(so + 0 * ARR_B, &edge_n4[base]);
            cp16(so + 1 * ARR_B, &edge_i4[base]);
            cp16(so + 2 * ARR_B, &edge_j4[base]);
            cp16(so + 3 * ARR_B, &sod4[base]);
        }
    };

    // Prologue: fill first stage.
    stage(blockIdx.x, 0);
    cp_commit();

    // Main pipelined loop: prefetch it+1 while consuming it.
    for (int it = 0; ; it++) {
        int blk_cons = blockIdx.x + it * gridDim.x;
        if (blk_cons >= nblk) break;

        stage(blockIdx.x + (it + 1) * gridDim.x, (it + 1) % STAGES);
        cp_commit();
        cp_wait<1>();   // our stage's group is complete

        long base = (long)blk_cons * THREADS + tid;
        if (base < nvec) {
            int s = it % STAGES;
            const char* sp = buf + (size_t)s * STG_B + (size_t)tid * 16;
            int4   en = *(const int4*)  (sp + 0 * ARR_B);
            int4   ei = *(const int4*)  (sp + 1 * ARR_B);
            int4   ej = *(const int4*)  (sp + 2 * ARR_B);
            float4 sd = *(const float4*)(sp + 3 * ARR_B);

            edge_op(en.x, ei.x, ej.x, sd.x, elm_s, pair, acc_base);
            edge_op(en.y, ei.y, ej.y, sd.y, elm_s, pair, acc_base);
            edge_op(en.z, ei.z, ej.z, sd.z, elm_s, pair, acc_base);
            edge_op(en.w, ei.w, ej.w, sd.w, elm_s, pair, acc_base);
        }
    }
    cp_wait<0>();

    // Scalar tail
    int gtid = blockIdx.x * THREADS + tid;
    int t = nvec * 4 + gtid;
    if (t < E)
        edge_op(edge_n[t], edge_i[t], edge_j[t], sod[t], elm_s, pair, acc_base);

    __syncthreads();

    // Reduce: first 256 threads; thread owns (bin = tid>>5, lane).
    if (tid < 256) {
        int bin = tid >> 5;
        float sum = 0.0f;
        #pragma unroll
        for (int w = 0; w < NWARP; w++)
            sum += acc[(w << 8) + (bin << 5) + lane];
        #pragma unroll
        for (int off = 16; off > 0; off >>= 1)
            sum += __shfl_down_sync(0xFFFFFFFFu, sum, off);
        if (lane == 0)
            atomicAdd(&out[bin], sum);
    }
}

// ---------------------------------------------------------------------------
// Launch
// ---------------------------------------------------------------------------
extern "C" void kernel_launch(void* const* d_in, const int* in_sizes, int n_in,
                              void* d_out, int out_size)
{
    const int*   elm    = (const int*)  d_in[0];
    const int*   edge_n = (const int*)  d_in[1];
    const int*   edge_i = (const int*)  d_in[2];
    const int*   edge_j = (const int*)  d_in[3];
    const float* sod    = (const float*)d_in[4];
    const float* k      = (const float*)d_in[5];
    const float* radius = (const float*)d_in[6];
    float* out = (float*)d_out;

    int E    = in_sizes[1];
    int nvec = E >> 2;

    cudaFuncSetAttribute(close_penalty_kernel,
                         cudaFuncAttributeMaxDynamicSharedMemorySize, SMEM_TOTAL);

    prep_kernel<<<(ELM_BYTES + 255) / 256, 256>>>(elm, out);

    int grid = GRID_MAIN;
    int nblk = (nvec + THREADS - 1) / THREADS;
    if (nblk < grid) grid = nblk > 0 ? nblk : 1;

    close_penalty_kernel<<<grid, THREADS, SMEM_TOTAL>>>(
        (const int4*)edge_n, (const int4*)edge_i, (const int4*)edge_j,
        (const float4*)sod,
        edge_n, edge_i, edge_j, sod,
        k, radius,
        out, nvec, E);
}

// round 12
// speedup vs baseline: 1.2047x; 1.0014x over previous
#include <cuda_runtime.h>
#include <cuda_fp16.h>
#include <stdint.h>

#define N_BCH 8
#define N_ATM 10000
#define N_ELM 100
#define THREADS 640
#define NWARP  20
#define GRID_MAIN 148            // 1 CTA per SM
#define STAGES 2

#define ELM_BYTES  (N_BCH * N_ATM)              // 80000
#define PAIR_N     (N_ELM * N_ELM)              // 10000
// smem layout (bytes)
#define SMEM_ACC   0                            // 8*640 floats = 20480
#define SMEM_PAIR  (8 * THREADS * 4)            // 40000
#define SMEM_ELM   (SMEM_PAIR + PAIR_N * 4)     // 80000
#define SMEM_BUF   (SMEM_ELM + ELM_BYTES)
#define ARR_B      (THREADS * 16)               // 10240
#define STG_B      (4 * ARR_B)                  // 40960
#define SMEM_TOTAL (SMEM_BUF + STAGES * STG_B)  // 222400

__device__ uint8_t g_elm8[ELM_BYTES];

__device__ __forceinline__ float fsqrt_approx(float x)
{
    float y;
    asm("sqrt.approx.f32 %0, %1;" : "=f"(y) : "f"(x));
    return y;
}

__device__ __forceinline__ void cp16(uint32_t saddr, const void* gptr)
{
    asm volatile("cp.async.cg.shared.global [%0], [%1], 16;\n"
                 :: "r"(saddr), "l"(gptr));
}
__device__ __forceinline__ void cp_commit()
{
    asm volatile("cp.async.commit_group;\n");
}
template <int N>
__device__ __forceinline__ void cp_wait()
{
    asm volatile("cp.async.wait_group %0;\n" :: "n"(N));
}

__device__ __forceinline__ uint32_t smem_u32(const void* p)
{
    uint32_t a;
    asm("{ .reg .u64 t; cvta.to.shared.u64 t, %1; cvt.u32.u64 %0, t; }"
        : "=r"(a) : "l"(p));
    return a;
}

// ---------------------------------------------------------------------------
// Prepass: zero outputs, convert elm int32 -> uint8 (values < 100).
// ---------------------------------------------------------------------------
__global__ void prep_kernel(const int* __restrict__ elm, float* __restrict__ out)
{
    int tid = blockIdx.x * blockDim.x + threadIdx.x;
    if (tid < N_BCH) out[tid] = 0.0f;
    for (int i = tid; i < ELM_BYTES; i += gridDim.x * blockDim.x)
        g_elm8[i] = (uint8_t)elm[i];
}

// ---------------------------------------------------------------------------
// Per-edge work: 2 u8 elm gathers + 1 half2 pair gather + smem RMW.
// ---------------------------------------------------------------------------
__device__ __forceinline__ void edge_op(int n, int i, int j, float s,
                                        const uint8_t* __restrict__ elm_s,
                                        const __half2* __restrict__ pair,
                                        float* __restrict__ acc_base)
{
    int nb = n * N_ATM;
    int ea = elm_s[nb + i];
    int eb = elm_s[nb + j];
    __half2 h = pair[ea * N_ELM + eb];
    float kk = __low2float(h);
    float R  = __high2float(h);
    float dis = fsqrt_approx(s);
    if (dis < R) {
        float d = dis - R;
        acc_base[n << 5] += kk * d * d;
    }
}

__global__ void __launch_bounds__(THREADS, 1)
close_penalty_kernel(const int4*  __restrict__ edge_n4,
                     const int4*  __restrict__ edge_i4,
                     const int4*  __restrict__ edge_j4,
                     const float4* __restrict__ sod4,
                     const int*   __restrict__ edge_n,
                     const int*   __restrict__ edge_i,
                     const int*   __restrict__ edge_j,
                     const float* __restrict__ sod,
                     const float* __restrict__ k,
                     const float* __restrict__ radius,
                     float* __restrict__ out,
                     int nvec, int E)
{
    extern __shared__ char smem[];
    float*   acc   = (float*)  (smem + SMEM_ACC);
    __half2* pair  = (__half2*)(smem + SMEM_PAIR);
    uint8_t* elm_s = (uint8_t*)(smem + SMEM_ELM);
    char*    buf   = smem + SMEM_BUF;

    int tid  = threadIdx.x;
    int lane = tid & 31;
    int wid  = tid >> 5;

    #pragma unroll
    for (int b = 0; b < 8; b++) acc[b * THREADS + tid] = 0.0f;

    // Build fused (kk, R) half2 pair table: 10000 entries.
    for (int idx = tid; idx < PAIR_N; idx += THREADS) {
        int a = idx / N_ELM;
        int b = idx - a * N_ELM;
        float kk = __ldg(&k[a]) + __ldg(&k[b]);
        float R  = __ldg(&radius[a]) + __ldg(&radius[b]);
        pair[idx] = __floats2half2_rn(kk, R);
    }

    // Copy 80 KB u8 element table into shared memory (16B chunks).
    {
        const int4* src = (const int4*)g_elm8;
        int4*       dst = (int4*)(smem + SMEM_ELM);
        for (int i = tid; i < ELM_BYTES / 16; i += THREADS)
            dst[i] = __ldg(&src[i]);
    }
    __syncthreads();

    float* acc_base = &acc[(wid << 8) | lane];   // + (n<<5) per edge

    uint32_t my_slot = smem_u32(buf) + (uint32_t)tid * 16;

    int nblk = (nvec + THREADS - 1) / THREADS;   // blocks of 640 vec4 groups

    auto stage = [&](int blk, int s) {
        long base = (long)blk * THREADS + tid;
        if (blk < nblk && base < nvec) {
            uint32_t so = my_slot + (uint32_t)s * STG_B;
            cp16(so + 0 * ARR_B, &edge_n4[base]);
            cp16(so + 1 * ARR_B, &edge_i4[base]);
            cp16(so + 2 * ARR_B, &edge_j4[base]);
            cp16(so + 3 * ARR_B, &sod4[base]);
        }
    };

    // Prologue: fill first stage.
    stage(blockIdx.x, 0);
    cp_commit();

    // Main pipelined loop: prefetch it+1 while consuming it.
    for (int it = 0; ; it++) {
        int blk_cons = blockIdx.x + it * gridDim.x;
        if (blk_cons >= nblk) break;

        stage(blockIdx.x + (it + 1) * gridDim.x, (it + 1) % STAGES);
        cp_commit();
        cp_wait<1>();   // our stage's group is complete

        long base = (long)blk_cons * THREADS + tid;
        if (base < nvec) {
            int s = it % STAGES;
            const char* sp = buf + (size_t)s * STG_B + (size_t)tid * 16;
            int4   en = *(const int4*)  (sp + 0 * ARR_B);
            int4   ei = *(const int4*)  (sp + 1 * ARR_B);
            int4   ej = *(const int4*)  (sp + 2 * ARR_B);
            float4 sd = *(const float4*)(sp + 3 * ARR_B);

            edge_op(en.x, ei.x, ej.x, sd.x, elm_s, pair, acc_base);
            edge_op(en.y, ei.y, ej.y, sd.y, elm_s, pair, acc_base);
            edge_op(en.z, ei.z, ej.z, sd.z, elm_s, pair, acc_base);
            edge_op(en.w, ei.w, ej.w, sd.w, elm_s, pair, acc_base);
        }
    }
    cp_wait<0>();

    // Scalar tail
    int gtid = blockIdx.x * THREADS + tid;
    int t = nvec * 4 + gtid;
    if (t < E)
        edge_op(edge_n[t], edge_i[t], edge_j[t], sod[t], elm_s, pair, acc_base);

    __syncthreads();

    // Reduce: first 256 threads; thread owns (bin = tid>>5, lane).
    if (tid < 256) {
        int bin = tid >> 5;
        float sum = 0.0f;
        #pragma unroll
        for (int w = 0; w < NWARP; w++)
            sum += acc[(w << 8) + (bin << 5) + lane];
        #pragma unroll
        for (int off = 16; off > 0; off >>= 1)
            sum += __shfl_down_sync(0xFFFFFFFFu, sum, off);
        if (lane == 0)
            atomicAdd(&out[bin], sum);
    }
}

// ---------------------------------------------------------------------------
// Launch
// ---------------------------------------------------------------------------
extern "C" void kernel_launch(void* const* d_in, const int* in_sizes, int n_in,
                              void* d_out, int out_size)
{
    const int*   elm    = (const int*)  d_in[0];
    const int*   edge_n = (const int*)  d_in[1];
    const int*   edge_i = (const int*)  d_in[2];
    const int*   edge_j = (const int*)  d_in[3];
    const float* sod    = (const float*)d_in[4];
    const float* k      = (const float*)d_in[5];
    const float* radius = (const float*)d_in[6];
    float* out = (float*)d_out;

    int E    = in_sizes[1];
    int nvec = E >> 2;

    cudaFuncSetAttribute(close_penalty_kernel,
                         cudaFuncAttributeMaxDynamicSharedMemorySize, SMEM_TOTAL);

    prep_kernel<<<(ELM_BYTES + 255) / 256, 256>>>(elm, out);

    int grid = GRID_MAIN;
    int nblk = (nvec + THREADS - 1) / THREADS;
    if (nblk < grid) grid = nblk > 0 ? nblk : 1;

    close_penalty_kernel<<<grid, THREADS, SMEM_TOTAL>>>(
        (const int4*)edge_n, (const int4*)edge_i, (const int4*)edge_j,
        (const float4*)sod,
        edge_n, edge_i, edge_j, sod,
        k, radius,
        out, nvec, E);
}